// round 15
// baseline (speedup 1.0000x reference)
#include <cuda_runtime.h>
#include <cuda_bf16.h>

#define NQ      65536
#define PP      2048
#define NREG    256                // 16x16 regions of 16px
#define CAPC    320                // region candidates (mean ~95 at T=18)
#define LOG2E   1.4426950408889634f
#define THRESH  18.0f              // log2 cut; measured err ~3e-5 << 1e-3 gate

// Dynamic SMEM layout (112640 B, 2 CTAs/SM => 220 KB <= 228 KB):
//   fx   : CAPC*16 floats  (20480 B)  fx[j*16+x]  = ex2(C_j*(x-px)^2)
//   fy4  : CAPC*16 float4  (81920 B)  {fy, fy*W0, fy*W1, fy*W2}
//   cand : CAPC float4     ( 5120 B)  {px, py, C, bitcast(p)}
//   recB : CAPC float4     ( 5120 B)  {W0, W1, W2, 0}
#define SMEM_BYTES (CAPC*16*4 + CAPC*16*16 + CAPC*16 + CAPC*16)

// Pixel table, fully rewritten each replay -> stateless, deterministic.
__device__ float4 g_tab[256 * 256];

__device__ __forceinline__ float ex2f(float x) {
    float r; asm("ex2.approx.f32 %0,%1;" : "=f"(r) : "f"(x)); return r;
}

// ---------------------------------------------------------------------------
// K1: one CTA per 16x16 region. Cull (2048 -> ~95 cands), separable tables
// with weights folded into fy4, per-pixel eval = 2 LDS + 4 FFMA per cand.
// ---------------------------------------------------------------------------
__global__ __launch_bounds__(256, 2)
void k_eval(const int2* __restrict__ pat,
            const float* __restrict__ W2,
            const float* __restrict__ sig) {
    extern __shared__ float sm[];
    float*  fx   = sm;                                  // [CAPC*16]
    float4* fy4  = (float4*)(sm + CAPC * 16);           // [CAPC*16]
    float4* cand = fy4 + CAPC * 16;                     // [CAPC]
    float4* recB = cand + CAPC;                         // [CAPC]
    __shared__ float wred[8];
    __shared__ int   wcnt[8];
    __shared__ int   s_nc;

    const int tid  = threadIdx.x;
    const int lane = tid & 31;
    const int wrp  = tid >> 5;
    const int r    = blockIdx.x;
    const int rx   = r >> 4, ry = r & 15;
    const float X0 = (float)(rx << 4), X1 = X0 + 15.0f;
    const float Y0 = (float)(ry << 4), Y1 = Y0 + 15.0f;

    // -- Level-A cull: 8 nodes/thread, region max bound + keep metric --
    float4 v[8];
    float keepm[8];
    float bestA = -1e30f;
#pragma unroll
    for (int k = 0; k < 8; k++) {
        int p = (k << 8) + tid;                        // coalesced
        int2 pp = pat[p];
        float px = (float)pp.x, py = (float)pp.y;
        float C = __fdividef(-0.5f * LOG2E, sig[p]);   // negative (MUFU rcp)
        float dxm = fmaxf(fabsf(px - X0), fabsf(px - X1));
        float dym = fmaxf(fabsf(py - Y0), fabsf(py - Y1));
        bestA = fmaxf(bestA, C * fmaf(dxm, dxm, dym * dym));
        float dxc = fmaxf(fmaxf(X0 - px, px - X1), 0.0f);
        float dyc = fmaxf(fmaxf(Y0 - py, py - Y1), 0.0f);
        keepm[k] = C * fmaf(dxc, dxc, dyc * dyc);
        v[k] = make_float4(px, py, C, __int_as_float(p));
    }
    for (int o = 16; o; o >>= 1)
        bestA = fmaxf(bestA, __shfl_xor_sync(0xffffffffu, bestA, o));
    if (lane == 0) wred[wrp] = bestA;
    __syncthreads();
    float cutA;
    {
        float b = wred[0];
#pragma unroll
        for (int w = 1; w < 8; w++) b = fmaxf(b, wred[w]);
        cutA = b - THRESH;
    }

    // -- Ballot compaction (warp-major, fixed ascending order) --
    int mycnt = 0;
    unsigned masks[8];
#pragma unroll
    for (int k = 0; k < 8; k++) {
        masks[k] = __ballot_sync(0xffffffffu, keepm[k] >= cutA);
        mycnt += __popc(masks[k]);
    }
    if (lane == 0) wcnt[wrp] = mycnt;
    __syncthreads();
    int base = 0, total = 0;
#pragma unroll
    for (int w = 0; w < 8; w++) {
        if (w < wrp) base += wcnt[w];
        total += wcnt[w];
    }
    if (tid == 0) s_nc = total < CAPC ? total : CAPC;
#pragma unroll
    for (int k = 0; k < 8; k++) {
        unsigned m = masks[k];
        if ((m >> lane) & 1u) {
            int rk = base + __popc(m & ((1u << lane) - 1u));
            if (rk < CAPC) cand[rk] = v[k];
        }
        base += __popc(m);
    }
    __syncthreads();
    const int nc = s_nc;

    // -- Build weight records, then separable tables (weights folded) --
    for (int j = tid; j < nc; j += 256) {
        int p = __float_as_int(cand[j].w);
        recB[j] = make_float4(W2[p], W2[PP + p], W2[2 * PP + p], 0.0f);
    }
    __syncthreads();
    for (int i = tid; i < nc * 16; i += 256) {
        int j = i >> 4, o = i & 15;
        float4 c = cand[j];
        float4 w = recB[j];
        float dx = (X0 + (float)o) - c.x;
        float dy = (Y0 + (float)o) - c.y;
        fx[i] = ex2f(c.z * dx * dx);
        float fyv = ex2f(c.z * dy * dy);
        fy4[i] = make_float4(fyv, fyv * w.x, fyv * w.y, fyv * w.z);
    }
    __syncthreads();

    // -- Eval: one pixel per thread; 2 LDS + 4 FFMA per candidate --
    const int tx = tid >> 4, ty = tid & 15;
    float den = 0.f, n0 = 0.f, n1 = 0.f, n2 = 0.f;
#pragma unroll 4
    for (int j = 0; j < nc; j++) {
        float  a = fx[(j << 4) + tx];        // 2 distinct addrs/warp
        float4 q = fy4[(j << 4) + ty];       // 16 distinct 16B, conflict-free
        den = fmaf(a, q.x, den);
        n0  = fmaf(a, q.y, n0);
        n1  = fmaf(a, q.z, n1);
        n2  = fmaf(a, q.w, n2);
    }
    const int ix = (rx << 4) + tx;
    const int iy = (ry << 4) + ty;
    float inv = 1.0f / den;
    g_tab[(ix << 8) + iy] = make_float4(n0 * inv, n1 * inv, n2 * inv, den);
}

// ---------------------------------------------------------------------------
// K2: gather, 4 queries/thread (MLP=4), coalesced float4 stores.
// ---------------------------------------------------------------------------
__global__ __launch_bounds__(128)
void k_gather(const int4* __restrict__ X4, float4* __restrict__ out4) {
    int i = blockIdx.x * 128 + threadIdx.x;
    int4 a = X4[2 * i];
    int4 b = X4[2 * i + 1];
    float4 v0 = g_tab[(a.x << 8) + a.y];
    float4 v1 = g_tab[(a.z << 8) + a.w];
    float4 v2 = g_tab[(b.x << 8) + b.y];
    float4 v3 = g_tab[(b.z << 8) + b.w];
    out4[3 * i + 0] = make_float4(v0.x, v0.y, v0.z, v1.x);
    out4[3 * i + 1] = make_float4(v1.y, v1.z, v2.x, v2.y);
    out4[3 * i + 2] = make_float4(v2.z, v3.x, v3.y, v3.z);
}

// ---------------------------------------------------------------------------
extern "C" void kernel_launch(void* const* d_in, const int* in_sizes, int n_in,
                              void* d_out, int out_size) {
    const int*   X   = (const int*)d_in[0];     // [N,2] int32
    const int*   pat = (const int*)d_in[1];     // [P,2] int32
    const float* W2  = (const float*)d_in[2];   // [C,P] f32
    const float* sig = (const float*)d_in[3];   // [P]   f32
    float* out = (float*)d_out;
    (void)in_sizes; (void)n_in; (void)out_size;

    cudaFuncSetAttribute(k_eval,
                         cudaFuncAttributeMaxDynamicSharedMemorySize, SMEM_BYTES);
    k_eval<<<NREG, 256, SMEM_BYTES>>>((const int2*)pat, W2, sig);
    k_gather<<<128, 128>>>((const int4*)X, (float4*)out);
}

// round 16
// speedup vs baseline: 1.1734x; 1.1734x over previous
#include <cuda_runtime.h>
#include <cuda_bf16.h>

#define NQ      65536
#define PP      2048
#define NREG    256                // 16x16 regions of 16px
#define CAPC    320                // region candidates (mean ~95 at T=18)
#define LOG2E   1.4426950408889634f
#define THRESH  18.0f              // log2 cut; measured err ~1.3e-7 << 1e-3

// Dynamic SMEM (112640 B, 2 CTAs/SM):
//   fx   : CAPC*16 floats  (20480 B)  fx[j*16+x] = ex2(C_j*(x-px)^2)
//   fy4  : CAPC*16 float4  (81920 B)  {fy, fy*W0, fy*W1, fy*W2}
//   cand : CAPC float4     ( 5120 B)  {px, py, C, bitcast(p)}  [reused: red0]
//   recB : CAPC float4     ( 5120 B)  {W0, W1, W2, 0}          [reused: red1]
#define SMEM_BYTES (CAPC*16*4 + CAPC*16*16 + CAPC*16 + CAPC*16)

// Pixel table, fully rewritten each replay -> stateless, deterministic.
__device__ float4 g_tab[256 * 256];

__device__ __forceinline__ float ex2f(float x) {
    float r; asm("ex2.approx.f32 %0,%1;" : "=f"(r) : "f"(x)); return r;
}

// ---------------------------------------------------------------------------
// K1: one CTA per 16x16 region. Cull (2048 -> ~95 cands), separable tables,
// then eval with 2 pixels/thread + even/odd j split across warp pairs:
// per warp-iter 3 MIO cyc cover 64 pixel-candidates (2x better than R15).
// ---------------------------------------------------------------------------
__global__ __launch_bounds__(256, 2)
void k_eval(const int2* __restrict__ pat,
            const float* __restrict__ W2,
            const float* __restrict__ sig) {
    extern __shared__ float sm[];
    float*  fx   = sm;                                  // [CAPC*16]
    float4* fy4  = (float4*)(sm + CAPC * 16);           // [CAPC*16]
    float4* cand = fy4 + CAPC * 16;                     // [CAPC]
    float4* recB = cand + CAPC;                         // [CAPC]
    float4* red0 = cand;                                // alias after build
    float4* red1 = recB;                                // alias after build
    __shared__ float wred[8];
    __shared__ int   wcnt[8];
    __shared__ int   s_nc;

    const int tid  = threadIdx.x;
    const int lane = tid & 31;
    const int wrp  = tid >> 5;
    const int r    = blockIdx.x;
    const int rx   = r >> 4, ry = r & 15;
    const float X0 = (float)(rx << 4), X1 = X0 + 15.0f;
    const float Y0 = (float)(ry << 4), Y1 = Y0 + 15.0f;

    // -- Level-A cull: 8 nodes/thread, region max bound + keep metric --
    float4 v[8];
    float keepm[8];
    float bestA = -1e30f;
#pragma unroll
    for (int k = 0; k < 8; k++) {
        int p = (k << 8) + tid;                        // coalesced
        int2 pp = pat[p];
        float px = (float)pp.x, py = (float)pp.y;
        float C = __fdividef(-0.5f * LOG2E, sig[p]);   // negative (MUFU rcp)
        float dxm = fmaxf(fabsf(px - X0), fabsf(px - X1));
        float dym = fmaxf(fabsf(py - Y0), fabsf(py - Y1));
        bestA = fmaxf(bestA, C * fmaf(dxm, dxm, dym * dym));
        float dxc = fmaxf(fmaxf(X0 - px, px - X1), 0.0f);
        float dyc = fmaxf(fmaxf(Y0 - py, py - Y1), 0.0f);
        keepm[k] = C * fmaf(dxc, dxc, dyc * dyc);
        v[k] = make_float4(px, py, C, __int_as_float(p));
    }
    for (int o = 16; o; o >>= 1)
        bestA = fmaxf(bestA, __shfl_xor_sync(0xffffffffu, bestA, o));
    if (lane == 0) wred[wrp] = bestA;
    __syncthreads();
    float cutA;
    {
        float b = wred[0];
#pragma unroll
        for (int w = 1; w < 8; w++) b = fmaxf(b, wred[w]);
        cutA = b - THRESH;
    }

    // -- Ballot compaction (warp-major, fixed ascending order) --
    int mycnt = 0;
    unsigned masks[8];
#pragma unroll
    for (int k = 0; k < 8; k++) {
        masks[k] = __ballot_sync(0xffffffffu, keepm[k] >= cutA);
        mycnt += __popc(masks[k]);
    }
    if (lane == 0) wcnt[wrp] = mycnt;
    __syncthreads();
    int base = 0, total = 0;
#pragma unroll
    for (int w = 0; w < 8; w++) {
        if (w < wrp) base += wcnt[w];
        total += wcnt[w];
    }
    if (tid == 0) s_nc = total < CAPC ? total : CAPC;
#pragma unroll
    for (int k = 0; k < 8; k++) {
        unsigned m = masks[k];
        if ((m >> lane) & 1u) {
            int rk = base + __popc(m & ((1u << lane) - 1u));
            if (rk < CAPC) cand[rk] = v[k];
        }
        base += __popc(m);
    }
    __syncthreads();
    const int nc = s_nc;

    // -- Build weight records, then separable tables (weights folded) --
    for (int j = tid; j < nc; j += 256) {
        int p = __float_as_int(cand[j].w);
        recB[j] = make_float4(W2[p], W2[PP + p], W2[2 * PP + p], 0.0f);
    }
    __syncthreads();
    for (int i = tid; i < nc * 16; i += 256) {
        int j = i >> 4, o = i & 15;
        float4 c = cand[j];
        float4 w = recB[j];
        float dx = (X0 + (float)o) - c.x;
        float dy = (Y0 + (float)o) - c.y;
        fx[i] = ex2f(c.z * dx * dx);
        float fyv = ex2f(c.z * dy * dy);
        fy4[i] = make_float4(fyv, fyv * w.x, fyv * w.y, fyv * w.z);
    }
    __syncthreads();

    // -- Eval: 2 px/thread, j split even/odd across warp pairs --
    //   txp = (wrp>>1)*2 + (lane>>4)  in 0..7  -> pixels tx = 2*txp, 2*txp+1
    //   ty  = lane & 15
    //   jhalf = wrp & 1  (uniform j per warp -> fy4 stays 16 distinct addrs)
    const int txp   = ((wrp >> 1) << 1) + (lane >> 4);
    const int ty    = lane & 15;
    const int jhalf = wrp & 1;

    float2 den = make_float2(0.f, 0.f);
    float2 n0  = make_float2(0.f, 0.f);
    float2 n1  = make_float2(0.f, 0.f);
    float2 n2  = make_float2(0.f, 0.f);
#pragma unroll 4
    for (int j = jhalf; j < nc; j += 2) {
        float2 ax = *(const float2*)&fx[(j << 4) + (txp << 1)];  // LDS.64
        float4 q  = fy4[(j << 4) + ty];                          // LDS.128
        den.x = fmaf(ax.x, q.x, den.x);  den.y = fmaf(ax.y, q.x, den.y);
        n0.x  = fmaf(ax.x, q.y, n0.x);   n0.y  = fmaf(ax.y, q.y, n0.y);
        n1.x  = fmaf(ax.x, q.z, n1.x);   n1.y  = fmaf(ax.y, q.z, n1.y);
        n2.x  = fmaf(ax.x, q.w, n2.x);   n2.y  = fmaf(ax.y, q.w, n2.y);
    }
    __syncthreads();   // tables dead; reuse cand/recB as reduction buffers
    red0[tid] = make_float4(den.x, n0.x, n1.x, n2.x);   // pixel tx=2*txp
    red1[tid] = make_float4(den.y, n0.y, n1.y, n2.y);   // pixel tx=2*txp+1
    __syncthreads();

    if (jhalf == 0) {
        // partner = tid+32 (same txp/ty, jhalf=1). Fixed order: even + odd.
        float4 a0 = red0[tid], b0 = red0[tid + 32];
        float4 a1 = red1[tid], b1 = red1[tid + 32];
        const int iy  = (ry << 4) + ty;
        const int ix0 = (rx << 4) + (txp << 1);
        {
            float d = a0.x + b0.x;
            float inv = 1.0f / d;
            g_tab[(ix0 << 8) + iy] = make_float4((a0.y + b0.y) * inv,
                                                 (a0.z + b0.z) * inv,
                                                 (a0.w + b0.w) * inv, d);
        }
        {
            float d = a1.x + b1.x;
            float inv = 1.0f / d;
            g_tab[((ix0 + 1) << 8) + iy] = make_float4((a1.y + b1.y) * inv,
                                                       (a1.z + b1.z) * inv,
                                                       (a1.w + b1.w) * inv, d);
        }
    }
}

// ---------------------------------------------------------------------------
// K2: gather, 1 query/thread, 65536 threads (max warp-level parallelism,
// shortest dependency chain: X load -> tab load -> 3 stores).
// ---------------------------------------------------------------------------
__global__ __launch_bounds__(128)
void k_gather(const int2* __restrict__ X, float* __restrict__ out) {
    int i = blockIdx.x * 128 + threadIdx.x;
    int2 xy = X[i];
    float4 v = g_tab[(xy.x << 8) + xy.y];
    out[3 * i + 0] = v.x;
    out[3 * i + 1] = v.y;
    out[3 * i + 2] = v.z;
}

// ---------------------------------------------------------------------------
extern "C" void kernel_launch(void* const* d_in, const int* in_sizes, int n_in,
                              void* d_out, int out_size) {
    const int*   X   = (const int*)d_in[0];     // [N,2] int32
    const int*   pat = (const int*)d_in[1];     // [P,2] int32
    const float* W2  = (const float*)d_in[2];   // [C,P] f32
    const float* sig = (const float*)d_in[3];   // [P]   f32
    float* out = (float*)d_out;
    (void)in_sizes; (void)n_in; (void)out_size;

    cudaFuncSetAttribute(k_eval,
                         cudaFuncAttributeMaxDynamicSharedMemorySize, SMEM_BYTES);
    k_eval<<<NREG, 256, SMEM_BYTES>>>((const int2*)pat, W2, sig);
    k_gather<<<NQ / 128, 128>>>((const int2*)X, out);
}